// round 4
// baseline (speedup 1.0000x reference)
#include <cuda_runtime.h>
#include <cstdint>

#define NB 32768
#define NT 64
#define NIN 4
#define NH 64

__device__ int g_idx[NB];

typedef unsigned long long u64;

__device__ __forceinline__ float sigf(float x) {
    float e = __expf(-x);
    return __fdividef(1.f, 1.f + e);
}
__device__ __forceinline__ float tanhfast(float x) {
    float e = __expf(-2.f * x);
    return __fdividef(2.f, 1.f + e) - 1.f;
}

// ---- f32x2 packed helpers (sm_100+); .b64 regs via "l" constraint ----
__device__ __forceinline__ u64 splat2(float w) {
    u64 d; asm("mov.b64 %0, {%1, %1};" : "=l"(d) : "f"(w)); return d;
}
__device__ __forceinline__ u64 pk2(float a, float b) {
    u64 d; asm("mov.b64 %0, {%1, %2};" : "=l"(d) : "f"(a), "f"(b)); return d;
}
__device__ __forceinline__ void upk2(u64 d, float& a, float& b) {
    asm("mov.b64 {%0, %1}, %2;" : "=f"(a), "=f"(b) : "l"(d));
}
__device__ __forceinline__ void fma2(u64& acc, u64 a, u64 b) {
    asm("fma.rn.f32x2 %0, %1, %2, %3;" : "=l"(acc) : "l"(a), "l"(b), "l"(acc));
}
__device__ __forceinline__ void lds_2x64(uint32_t addr, u64& a, u64& b) {
    asm volatile("ld.shared.v2.b64 {%0, %1}, [%2];" : "=l"(a), "=l"(b) : "r"(addr));
}
__device__ __forceinline__ u64 lds_64(uint32_t addr) {
    u64 d; asm volatile("ld.shared.b64 %0, [%1];" : "=l"(d) : "r"(addr)); return d;
}
__device__ __forceinline__ void sts_64(uint32_t addr, u64 v) {
    asm volatile("st.shared.b64 [%0], %1;" :: "r"(addr), "l"(v) : "memory");
}

struct SmemGRU {
    float Whh[192][68];   // 272B row stride: 17×16B -> conflict-free LDS.128
    float Wih[192][4];
    float Br[64], Bz[64], Bin[64], Bhn[64];
    float Whd[4][64];
    float bhd[4];
    float H[4][64][12];   // [warp][k][8 samples + pad4]; 48B rows -> 16B-aligned v2.b64
};

// 128 threads = 4 warps; warp = 8 samples (4 f32x2 pairs); grid = 1024.
__global__ void __launch_bounds__(128) gru_sel_kernel(
    const float* __restrict__ Hn,
    const float* __restrict__ gum,
    const float* __restrict__ Wih,
    const float* __restrict__ Whh,
    const float* __restrict__ bih,
    const float* __restrict__ bhh,
    const float* __restrict__ Whead,
    const float* __restrict__ bhead,
    float* __restrict__ out)
{
    extern __shared__ char smem_raw[];
    SmemGRU& S = *reinterpret_cast<SmemGRU*>(smem_raw);
    const int tid = threadIdx.x;

    for (int i = tid; i < 192 * 64; i += 128) S.Whh[i >> 6][i & 63] = Whh[i];
    for (int i = tid; i < 192 * 4;  i += 128) S.Wih[i >> 2][i & 3]  = Wih[i];
    if (tid < 64) {
        S.Br[tid]  = bih[tid]        + bhh[tid];
        S.Bz[tid]  = bih[64 + tid]   + bhh[64 + tid];
        S.Bin[tid] = bih[128 + tid];
        S.Bhn[tid] = bhh[128 + tid];
    }
    for (int i = tid; i < 256; i += 128) S.Whd[i >> 6][i & 63] = Whead[i];
    if (tid < 4) S.bhd[tid] = bhead[tid];
    for (int i = tid; i < 4 * 64 * 12; i += 128) ((float*)S.H)[i] = 0.f;
    __syncthreads();

    const int w = tid >> 5, lane = tid & 31;
    const int u0 = lane, u1 = lane + 32;
    const int b0 = (blockIdx.x * 4 + w) * 8;
    const float* hp = Hn + (size_t)b0 * NT * NIN;

    const uint32_t Hb = (uint32_t)__cvta_generic_to_shared(&S.H[w][0][0]);
    const uint32_t Hu0 = Hb + u0 * 48, Hu1 = Hb + u1 * 48;

    // loop-invariant bias splats
    const u64 br0 = splat2(S.Br[u0]),  br1 = splat2(S.Br[u1]);
    const u64 bz0 = splat2(S.Bz[u0]),  bz1 = splat2(S.Bz[u1]);
    const u64 bi0 = splat2(S.Bin[u0]), bi1 = splat2(S.Bin[u1]);
    const u64 bh0 = splat2(S.Bhn[u0]), bh1 = splat2(S.Bhn[u1]);
    // input weights (tiny, keep in regs across t)
    const float4 wiR0 = *(const float4*)S.Wih[u0];
    const float4 wiZ0 = *(const float4*)S.Wih[u0 + 64];
    const float4 wiN0 = *(const float4*)S.Wih[u0 + 128];
    const float4 wiR1 = *(const float4*)S.Wih[u1];
    const float4 wiZ1 = *(const float4*)S.Wih[u1 + 64];
    const float4 wiN1 = *(const float4*)S.Wih[u1 + 128];

    u64 ar[2][4], az[2][4], ahn[2][4], ain[2][4];

#pragma unroll 1
    for (int t = 0; t < NT; t++) {
        // ---- input phase: pack x into sample-pair lanes ----
        u64 xp[4][4];   // [k][sp]
#pragma unroll
        for (int sp = 0; sp < 4; sp++) {
            const float4 xa = __ldg((const float4*)(hp + ((size_t)(2 * sp)     * NT + t) * NIN));
            const float4 xb = __ldg((const float4*)(hp + ((size_t)(2 * sp + 1) * NT + t) * NIN));
            xp[0][sp] = pk2(xa.x, xb.x);
            xp[1][sp] = pk2(xa.y, xb.y);
            xp[2][sp] = pk2(xa.z, xb.z);
            xp[3][sp] = pk2(xa.w, xb.w);
        }
#define IROW(W4, ACC, BIAS)                                              \
        {   const u64 s0 = splat2((W4).x), s1 = splat2((W4).y),           \
                      s2 = splat2((W4).z), s3 = splat2((W4).w);           \
            _Pragma("unroll")                                             \
            for (int sp = 0; sp < 4; sp++) {                              \
                ACC[sp] = BIAS;                                           \
                fma2(ACC[sp], s0, xp[0][sp]);                             \
                fma2(ACC[sp], s1, xp[1][sp]);                             \
                fma2(ACC[sp], s2, xp[2][sp]);                             \
                fma2(ACC[sp], s3, xp[3][sp]);                             \
            } }
        IROW(wiR0, ar[0], br0)  IROW(wiZ0, az[0], bz0)  IROW(wiN0, ain[0], bi0)
        IROW(wiR1, ar[1], br1)  IROW(wiZ1, az[1], bz1)  IROW(wiN1, ain[1], bi1)
#pragma unroll
        for (int sp = 0; sp < 4; sp++) { ahn[0][sp] = bh0; ahn[1][sp] = bh1; }

        // ---- recurrence: 6 gate rows x 64-dot, f32x2 over sample pairs ----
#pragma unroll 4
        for (int kc = 0; kc < NH; kc += 4) {
            u64 hk[4][4];   // [k][sp], broadcast loads
#pragma unroll
            for (int k = 0; k < 4; k++) {
                const uint32_t a = Hb + (kc + k) * 48;
                lds_2x64(a,      hk[k][0], hk[k][1]);
                lds_2x64(a + 16, hk[k][2], hk[k][3]);
            }
#define RROW(ROW, ACC)                                                    \
            {   const float4 w4 = *(const float4*)&S.Whh[ROW][kc];        \
                const u64 s0 = splat2(w4.x), s1 = splat2(w4.y),           \
                          s2 = splat2(w4.z), s3 = splat2(w4.w);           \
                _Pragma("unroll")                                         \
                for (int sp = 0; sp < 4; sp++) {                          \
                    fma2(ACC[sp], s0, hk[0][sp]);                         \
                    fma2(ACC[sp], s1, hk[1][sp]);                         \
                    fma2(ACC[sp], s2, hk[2][sp]);                         \
                    fma2(ACC[sp], s3, hk[3][sp]);                         \
                } }
            RROW(u0,       ar[0])
            RROW(u0 + 64,  az[0])
            RROW(u0 + 128, ahn[0])
            RROW(u1,       ar[1])
            RROW(u1 + 64,  az[1])
            RROW(u1 + 128, ahn[1])
        }
        __syncwarp();   // all lanes finished reading old H

        // ---- activations (scalar, MUFU pipe) ----
#pragma unroll
        for (int un = 0; un < 2; un++) {
            const uint32_t Hu = un ? Hu1 : Hu0;
#pragma unroll
            for (int sp = 0; sp < 4; sp++) {
                float a0, a1, z0f, z1f, i0, i1, n0h, n1h;
                upk2(ar[un][sp],  a0,  a1);
                upk2(az[un][sp],  z0f, z1f);
                upk2(ain[un][sp], i0,  i1);
                upk2(ahn[un][sp], n0h, n1h);
                float ho0, ho1;
                upk2(lds_64(Hu + sp * 8), ho0, ho1);
                const float r0 = sigf(a0), r1 = sigf(a1);
                const float zz0 = sigf(z0f), zz1 = sigf(z1f);
                const float n0 = tanhfast(i0 + r0 * n0h);
                const float n1 = tanhfast(i1 + r1 * n1h);
                const float h0 = n0 + zz0 * (ho0 - n0);
                const float h1 = n1 + zz1 * (ho1 - n1);
                sts_64(Hu + sp * 8, pk2(h0, h1));
            }
        }
        __syncwarp();   // new h visible to all lanes
    }

    // ---- head + gumbel argmax: lane -> (sample = lane>>2, mode = lane&3) ----
    const int sl = lane >> 2, ml = lane & 3;
    float acc = S.bhd[ml];
#pragma unroll
    for (int k = 0; k < NH; k++)
        acc += S.Whd[ml][k] * S.H[w][k][sl];
    const int b = b0 + sl;
    const float lv = acc + __ldg(&gum[b * 4 + ml]);
    float best = lv;
    int   bi   = ml;
#pragma unroll
    for (int d = 1; d < 4; d <<= 1) {
        const float ob = __shfl_xor_sync(0xffffffffu, best, d);
        const int   oi = __shfl_xor_sync(0xffffffffu, bi, d);
        if (ob > best || (ob == best && oi < bi)) { best = ob; bi = oi; }
    }
    out[131072 + b * 4 + ml] = acc;                       // logits
    out[262144 + b * 4 + ml] = (ml == bi) ? 1.f : 0.f;    // onehot
    if (ml == 0) { out[393216 + b] = (float)bi; g_idx[b] = bi; }
}

// Expert bank: unchanged (35us, not the bottleneck).
__global__ void __launch_bounds__(256) bank_kernel(
    const float* __restrict__ Xp,
    const float* __restrict__ dtp,
    const float* __restrict__ W1,
    const float* __restrict__ b1,
    const float* __restrict__ W2,
    const float* __restrict__ b2,
    float* __restrict__ out)
{
    __shared__ float sW1[4 * 5 * 256];
    __shared__ float sb1[4 * 256];
    __shared__ float sW2[4][256][5];
    __shared__ float sb2[16];
    const int tid = threadIdx.x;
    for (int i = tid; i < 5120; i += 256) sW1[i] = W1[i];
    for (int i = tid; i < 1024; i += 256) sb1[i] = b1[i];
    for (int i = tid; i < 4096; i += 256) sW2[i >> 10][(i >> 2) & 255][i & 3] = W2[i];
    if (tid < 16) sb2[tid] = b2[tid];
    __syncthreads();

    const float dt = __ldg(dtp);
    const int gw = blockIdx.x * 8 + (tid >> 5);
    const int lane = tid & 31;
#pragma unroll 1
    for (int it = 0; it < 8; it++) {
        const int b = gw * 8 + it;
        const int e = g_idx[b];
        const float4 xv = __ldg((const float4*)(Xp + b * 4));
        const float* w1e = sW1 + e * 1280;
        float hid[8];
#pragma unroll
        for (int j = 0; j < 8; j++) {
            const int u = lane + 32 * j;
            float a = sb1[e * 256 + u]
                    + xv.x * w1e[0 * 256 + u]
                    + xv.y * w1e[1 * 256 + u]
                    + xv.z * w1e[2 * 256 + u]
                    + xv.w * w1e[3 * 256 + u]
                    + dt   * w1e[4 * 256 + u];
            hid[j] = tanhfast(a);
        }
        float f0 = 0.f, f1 = 0.f, f2 = 0.f, f3 = 0.f;
#pragma unroll
        for (int j = 0; j < 8; j++) {
            const int u = lane + 32 * j;
            f0 += hid[j] * sW2[e][u][0];
            f1 += hid[j] * sW2[e][u][1];
            f2 += hid[j] * sW2[e][u][2];
            f3 += hid[j] * sW2[e][u][3];
        }
#pragma unroll
        for (int off = 16; off >= 1; off >>= 1) {
            f0 += __shfl_xor_sync(0xffffffffu, f0, off);
            f1 += __shfl_xor_sync(0xffffffffu, f1, off);
            f2 += __shfl_xor_sync(0xffffffffu, f2, off);
            f3 += __shfl_xor_sync(0xffffffffu, f3, off);
        }
        if (lane < 4) {
            float fv = (lane == 0) ? f0 : (lane == 1) ? f1 : (lane == 2) ? f2 : f3;
            fv += sb2[e * 4 + lane];
            out[b * 4 + lane] = __ldg(&Xp[b * 4 + lane]) + dt * fv;
        }
    }
}

extern "C" void kernel_launch(void* const* d_in, const int* in_sizes, int n_in,
                              void* d_out, int out_size) {
    const float* Hn    = (const float*)d_in[0];
    const float* Xp    = (const float*)d_in[1];
    const float* dtp   = (const float*)d_in[2];
    const float* gum   = (const float*)d_in[3];
    const float* Wih   = (const float*)d_in[4];
    const float* Whh   = (const float*)d_in[5];
    const float* bih   = (const float*)d_in[6];
    const float* bhh   = (const float*)d_in[7];
    const float* Whead = (const float*)d_in[8];
    const float* bhead = (const float*)d_in[9];
    const float* W1    = (const float*)d_in[10];
    const float* b1    = (const float*)d_in[11];
    const float* W2    = (const float*)d_in[12];
    const float* b2    = (const float*)d_in[13];
    float* out = (float*)d_out;

    const int smem = (int)sizeof(SmemGRU);
    cudaFuncSetAttribute(gru_sel_kernel, cudaFuncAttributeMaxDynamicSharedMemorySize, smem);

    gru_sel_kernel<<<1024, 128, smem>>>(Hn, gum, Wih, Whh, bih, bhh, Whead, bhead, out);
    bank_kernel<<<512, 256>>>(Xp, dtp, W1, b1, W2, b2, out);
}